// round 15
// baseline (speedup 1.0000x reference)
#include <cuda_runtime.h>
#include <cuda_fp16.h>
#include <math.h>
#include <stdint.h>

#define DIMK   256
#define LATENT 1024
#define BB     128
#define TT     512
#define KB     2048          // B' (scan) columns: [hi | lo] fp16
#define NCTA   128

// ---------------------------------------------------------------------------
// Scratch (__device__ globals — no allocations allowed)
// ---------------------------------------------------------------------------
__device__ __half g_B[LATENT * KB];                 // scan B' = WhT split [n][hi1024|lo1024]
__device__ __half g_Ah[2][BB * LATENT];             // scan A = fp16(h), ping-pong [m][1024]
__device__ __half g_X[(size_t)BB * TT * DIMK];      // gemm1 A = fp16(x) [r][256]
__device__ __half g_BX[LATENT * 512];               // gemm1 B' = WxT split [n][hi256|lo256]
__device__ unsigned g_bar_m[128];                   // 4 m-group counters, 128B apart

__device__ __forceinline__ uint32_t smem_u32(const void* p) {
    uint32_t a;
    asm("{ .reg .u64 t; cvta.to.shared.u64 t, %1; cvt.u32.u64 %0, t; }" : "=r"(a) : "l"(p));
    return a;
}
__device__ __forceinline__ void cp16(uint32_t dst, const void* src) {
    asm volatile("cp.async.cg.shared.global [%0], [%1], 16;" :: "r"(dst), "l"(src));
}
__device__ __forceinline__ uint32_t pack_h2(float a, float b) {
    __half2 h = __floats2half2_rn(a, b);
    return *reinterpret_cast<uint32_t*>(&h);
}
#define CP_COMMIT() asm volatile("cp.async.commit_group;")
#define CP_WAIT(n)  asm volatile("cp.async.wait_group %0;" :: "n"(n))

#define LDSM4(r0, r1, r2, r3, addr) \
    asm volatile("ldmatrix.sync.aligned.m8n8.x4.shared.b16 {%0,%1,%2,%3}, [%4];" \
                 : "=r"(r0), "=r"(r1), "=r"(r2), "=r"(r3) : "r"(addr))
#define MMAF16(d, a0, a1, a2, a3, b0, b1) \
    asm volatile("mma.sync.aligned.m16n8k16.row.col.f32.f16.f16.f32 " \
                 "{%0,%1,%2,%3}, {%4,%5,%6,%7}, {%8,%9}, {%0,%1,%2,%3};" \
                 : "+f"((d)[0]), "+f"((d)[1]), "+f"((d)[2]), "+f"((d)[3]) \
                 : "r"(a0), "r"(a1), "r"(a2), "r"(a3), "r"(b0), "r"(b1))

// ---------------------------------------------------------------------------
// prep: Wh[k][n] -> g_B[n][k]=fp16 hi, g_B[n][1024+k]=fp16 lo
// ---------------------------------------------------------------------------
__global__ void prep_wh_kernel(const float* __restrict__ W) {
    const float* Wh = W + (size_t)DIMK * LATENT;
    __shared__ float tile[32][33];
    int bx = blockIdx.x * 32;
    int by = blockIdx.y * 32;
    int tx = threadIdx.x, ty = threadIdx.y;
    #pragma unroll
    for (int i = ty; i < 32; i += 8)
        tile[i][tx] = Wh[(size_t)(by + i) * LATENT + bx + tx];
    __syncthreads();
    #pragma unroll
    for (int i = ty; i < 32; i += 8) {
        float v = tile[tx][i];
        size_t o = (size_t)(bx + i) * KB + by + tx;
        __half h = __float2half_rn(v);
        g_B[o]        = h;
        g_B[o + 1024] = __float2half_rn(v - __half2float(h));
    }
}

// ---------------------------------------------------------------------------
// prep: Wx[k][n] (k<256) -> g_BX[n][k]=fp16 hi, [n][256+k]=fp16 lo
// ---------------------------------------------------------------------------
__global__ void prep_bx_kernel(const float* __restrict__ W) {
    __shared__ float tile[32][33];
    int bx = blockIdx.x * 32;
    int by = blockIdx.y * 32;
    int tx = threadIdx.x, ty = threadIdx.y;
    #pragma unroll
    for (int i = ty; i < 32; i += 8)
        tile[i][tx] = W[(size_t)(by + i) * LATENT + bx + tx];
    __syncthreads();
    #pragma unroll
    for (int i = ty; i < 32; i += 8) {
        float v = tile[tx][i];
        size_t o = (size_t)(bx + i) * 512 + by + tx;
        __half h = __float2half_rn(v);
        g_BX[o]       = h;
        g_BX[o + 256] = __float2half_rn(v - __half2float(h));
    }
}

// ---------------------------------------------------------------------------
// prep: x[r][d] fp32 -> g_X[r][d] = fp16(x) (unsplit; error carried by W split)
// ---------------------------------------------------------------------------
__global__ void prep_x_kernel(const float* __restrict__ x) {
    size_t idx = (size_t)blockIdx.x * 256 + threadIdx.x;
    size_t e = idx * 4;
    float4 v = *reinterpret_cast<const float4*>(x + e);
    *reinterpret_cast<uint32_t*>(&g_X[e + 0]) = pack_h2(v.x, v.y);
    *reinterpret_cast<uint32_t*>(&g_X[e + 2]) = pack_h2(v.z, v.w);
}

// ---------------------------------------------------------------------------
// GEMM1 (tensor, fp16; round-12 config — 258us): out[t,b,:] = x @ Wx + b.
// K'=512 ([Whi256|Wlo256], A=fp16 x unsplit). CTA 64 rows, warp 32x16,
// A resident 32KB, B double-buffered 2x16KB, 2 CTAs/SM.
// ---------------------------------------------------------------------------
#define G1_SMB   32768
#define G1_SMEM  (32768 + 2 * 16384)

__global__ void __launch_bounds__(256, 2)
gemm1_mma_kernel(const float* __restrict__ bias, float* __restrict__ out) {
    extern __shared__ char smem[];
    const uint32_t smA = smem_u32(smem);
    const uint32_t smB = smA + G1_SMB;
    const int tid = threadIdx.x;
    const int lid = tid & 31;
    const int wid = tid >> 5;
    const int r0 = blockIdx.x * 64;

    {
        const __half* gA = g_X + (size_t)r0 * DIMK;
        #pragma unroll
        for (int j = 0; j < 8; ++j) {
            int ci = tid + j * 256;
            int ch = ci >> 10;
            int rem = ci & 1023;
            int rw = rem >> 4;
            int cc = rem & 15;
            cp16(smA + ch * 16384 + rw * 256 + (((cc ^ (rw & 15))) << 4),
                 gA + (size_t)rw * DIMK + ch * 128 + cc * 8);
        }
        CP_COMMIT();
    }
    {
        #pragma unroll
        for (int j = 0; j < 4; ++j) {
            int ci = tid + j * 256;
            int rw = ci >> 4;
            int cc = ci & 15;
            cp16(smB + rw * 256 + (((cc ^ (rw & 15))) << 4),
                 g_BX + (size_t)rw * 512 + cc * 8);
        }
        CP_COMMIT();
    }

    const int wm = wid & 1;
    const int wn = wid >> 1;
    const int a_row0 = wm * 32 + (lid & 15);
    const int a_row1 = a_row0 + 16;
    const int a_kh   = (lid >> 4) & 1;
    const int b_row  = wn * 16 + (((lid >> 4) & 1) << 3) + (lid & 7);
    const int b_kh   = (lid >> 3) & 1;
    const int a_swz0 = a_row0 & 15, a_swz1 = a_row1 & 15, b_swz = b_row & 15;
    const int g8 = lid >> 2;
    const int q  = lid & 3;

    float acc[4][4];

    #pragma unroll 1
    for (int gg = 0; gg < 64; ++gg) {
        const int nt = gg >> 2;
        const int c  = gg & 3;

        if (gg + 1 < 64) {
            const int nt2 = (gg + 1) >> 2;
            const int c2  = (gg + 1) & 3;
            const int cb  = c2 * 128;
            uint32_t dst = smB + ((gg + 1) & 1) * 16384;
            const __half* gBn = g_BX + (size_t)(nt2 * 64) * 512;
            #pragma unroll
            for (int j = 0; j < 4; ++j) {
                int ci = tid + j * 256;
                int rw = ci >> 4;
                int cc = ci & 15;
                cp16(dst + rw * 256 + (((cc ^ (rw & 15))) << 4),
                     gBn + (size_t)rw * 512 + cb + cc * 8);
            }
            CP_COMMIT();
            CP_WAIT(1);
        } else {
            CP_WAIT(0);
        }
        __syncthreads();

        if (c == 0) {
            #pragma unroll
            for (int i = 0; i < 4; ++i)
                #pragma unroll
                for (int j = 0; j < 4; ++j) acc[i][j] = 0.f;
        }

        const int ach = c & 1;
        const uint32_t aR0 = smA + ach * 16384 + a_row0 * 256;
        const uint32_t aR1 = smA + ach * 16384 + a_row1 * 256;
        const uint32_t bR  = smB + (gg & 1) * 16384 + b_row * 256;

        #pragma unroll
        for (int s = 0; s < 8; ++s) {
            uint32_t A0, A1, A2, A3, C0, C1, C2, C3, B0, B1, B2, B3;
            LDSM4(A0, A1, A2, A3, aR0 + (((2 * s + a_kh) ^ a_swz0) << 4));
            LDSM4(C0, C1, C2, C3, aR1 + (((2 * s + a_kh) ^ a_swz1) << 4));
            LDSM4(B0, B1, B2, B3, bR  + (((2 * s + b_kh) ^ b_swz) << 4));
            MMAF16(acc[0], A0, A1, A2, A3, B0, B1);
            MMAF16(acc[1], A0, A1, A2, A3, B2, B3);
            MMAF16(acc[2], C0, C1, C2, C3, B0, B1);
            MMAF16(acc[3], C0, C1, C2, C3, B2, B3);
        }

        if (c == 3) {
            const int n0 = nt * 64;
            #pragma unroll
            for (int f = 0; f < 2; ++f) {
                #pragma unroll
                for (int ntf = 0; ntf < 2; ++ntf) {
                    const int col = n0 + wn * 16 + ntf * 8 + q * 2;
                    float2 bv = *reinterpret_cast<const float2*>(bias + col);
                    #pragma unroll
                    for (int rh = 0; rh < 2; ++rh) {
                        const int r = r0 + wm * 32 + f * 16 + g8 + rh * 8;
                        const int bi = r >> 9;
                        const int ti = r & (TT - 1);
                        float2 o;
                        o.x = acc[f * 2 + ntf][rh * 2 + 0] + bv.x;
                        o.y = acc[f * 2 + ntf][rh * 2 + 1] + bv.y;
                        *reinterpret_cast<float2*>(
                            &out[((size_t)ti * BB + bi) * LATENT + col]) = o;
                    }
                }
            }
        }
        __syncthreads();
    }
}

// ---------------------------------------------------------------------------
// t = 0: out[0] = tanh(out[0]); h0 -> g_Ah[0] fp16; reset m-group barriers
// ---------------------------------------------------------------------------
__global__ void tanh0_kernel(float* __restrict__ out0) {
    int i = blockIdx.x * blockDim.x + threadIdx.x;
    if (i < 4) g_bar_m[i * 32] = 0;
    float v = tanhf(out0[i]);
    out0[i] = v;
    g_Ah[0][i] = __float2half_rn(v);
}

// ---------------------------------------------------------------------------
// Persistent scan: 128 CTAs (4m x 32n tiles of 32x32), 256 threads = 8 warps.
// 8-way split-K, 2 fp16 terms: A*Bhi(reg) + A*Blo(smem), A = fp16(h) unsplit.
// This round: dedicated partials buffer (warp-private A + partials slots ->
// only 2 block syncs/step), warp-level barrier release (each warp's lane 0
// polls the m-group counter and proceeds straight to its own staging).
// ---------------------------------------------------------------------------
#define SCAN_A    65536                       // A region: 8 x 8KB (after Blo 8 x 8KB)
#define SCAN_P    131072                      // partials: 8 warps x 4608B
#define SMEM_SCAN (131072 + 8 * 4608)         // 167936

__global__ void __launch_bounds__(256, 1)
scan_kernel(float* __restrict__ out) {
    extern __shared__ char smem[];
    const int tid = threadIdx.x;
    const int lid = tid & 31;
    const int wid = tid >> 5;
    const int bid = blockIdx.x;
    const int mg = bid & 3;
    const int m0 = mg * 32;
    const int n0 = (bid >> 2) * 32;
    const uint32_t smB = smem_u32(smem);
    const uint32_t smA = smB + SCAN_A;
    const uint32_t abase = smA + wid * 8192;      // this warp's A slot (32 rows x 256B)

    // ---- B geometry ----
    const int b_r  = (((lid >> 4) & 1) << 3) + (lid & 7);
    const int b_kh = (lid >> 3) & 1;
    const int b_swz = b_r & 15;
    // ---- A geometry ----
    const int a_r  = lid & 15;
    const int a_kh = (lid >> 4) & 1;
    const int a_swz = a_r & 15;

    // ---- init: warp w stages B-lo chunk w (resident) + B-hi chunk w (temp) ----
    {
        const __half* gB = g_B + (size_t)n0 * KB;
        #pragma unroll
        for (int j = 0; j < 16; ++j) {
            int ci = lid + j * 32;        // 0..511
            int rw = ci >> 4;
            int cc = ci & 15;
            uint32_t sw = ((cc ^ (rw & 15)) << 4);
            cp16(smB + wid * 8192 + rw * 256 + sw,
                 gB + (size_t)rw * KB + 1024 + wid * 128 + cc * 8);   // lo
            cp16(abase + rw * 256 + sw,
                 gB + (size_t)rw * KB + wid * 128 + cc * 8);          // hi (temp)
        }
        CP_COMMIT();
        CP_WAIT(0);
        __syncwarp();
    }

    // ---- B-hi fragments into registers (constant for all 511 steps) ----
    uint32_t bhi[8][8];
    #pragma unroll
    for (int s = 0; s < 8; ++s) {
        const uint32_t off = ((uint32_t)((2 * s + b_kh) ^ b_swz)) << 4;
        LDSM4(bhi[s][0], bhi[s][1], bhi[s][2], bhi[s][3], abase + b_r * 256 + off);
        LDSM4(bhi[s][4], bhi[s][5], bhi[s][6], bhi[s][7], abase + (b_r + 16) * 256 + off);
    }
    __syncwarp();

    // ---- epilogue geometry ----
    const int e_row = tid >> 3;            // 0..31
    const int e_cg  = (tid & 7) * 4;       // 0..28
    const int gm = m0 + e_row;
    const int e0 = n0 + e_cg;
    volatile unsigned* barp = &g_bar_m[mg * 32];

    for (int t = 1; t < TT; ++t) {
        const int rp = (t - 1) & 1;
        const __half* Ar = g_Ah[rp];
        __half* Aw = g_Ah[rp ^ 1];
        float* out_t = out + (size_t)t * BB * LATENT;

        // ---- self-stage A chunk: group 0 = rows 0-15, group 1 = rows 16-31 ----
        #pragma unroll
        for (int j = 0; j < 8; ++j) {
            int ci = lid + j * 32;            // 0..255
            int rw = ci >> 4;                 // 0..15
            int cc = ci & 15;
            cp16(abase + rw * 256 + ((cc ^ (rw & 15)) << 4),
                 Ar + (size_t)(m0 + rw) * LATENT + wid * 128 + cc * 8);
        }
        CP_COMMIT();
        #pragma unroll
        for (int j = 0; j < 8; ++j) {
            int ci = lid + j * 32;
            int rw = ci >> 4;
            int cc = ci & 15;
            cp16(abase + 4096 + rw * 256 + ((cc ^ (rw & 15)) << 4),
                 Ar + (size_t)(m0 + 16 + rw) * LATENT + wid * 128 + cc * 8);
        }
        CP_COMMIT();

        // ---- xw prefetch (hidden under staging + MMA) ----
        const float4 xv = *reinterpret_cast<const float4*>(
            out_t + (size_t)gm * LATENT + e0);

        float acc[32];
        #pragma unroll
        for (int i = 0; i < 32; ++i) acc[i] = 0.f;

        const uint32_t aH = abase + a_r * 256;
        const uint32_t bLo = smB + wid * 8192 + b_r * 256;

        // ---- phase 1: m-frag0 (rows 0-15) while group 1 streams in ----
        CP_WAIT(1);
        __syncwarp();
        #pragma unroll
        for (int s = 0; s < 8; ++s) {
            const uint32_t aoff = ((uint32_t)((2 * s + a_kh) ^ a_swz)) << 4;
            const uint32_t boff = ((uint32_t)((2 * s + b_kh) ^ b_swz)) << 4;
            uint32_t A0[4], blo[8];
            LDSM4(A0[0], A0[1], A0[2], A0[3], aH + aoff);
            LDSM4(blo[0], blo[1], blo[2], blo[3], bLo + boff);
            LDSM4(blo[4], blo[5], blo[6], blo[7], bLo + 16 * 256 + boff);
            #pragma unroll
            for (int ni = 0; ni < 4; ++ni) {
                MMAF16(acc + ni * 4, A0[0], A0[1], A0[2], A0[3],
                       bhi[s][ni * 2], bhi[s][ni * 2 + 1]);
                MMAF16(acc + ni * 4, A0[0], A0[1], A0[2], A0[3],
                       blo[ni * 2], blo[ni * 2 + 1]);
            }
        }

        // ---- phase 2: m-frag1 (rows 16-31) ----
        CP_WAIT(0);
        __syncwarp();
        #pragma unroll
        for (int s = 0; s < 8; ++s) {
            const uint32_t aoff = ((uint32_t)((2 * s + a_kh) ^ a_swz)) << 4;
            const uint32_t boff = ((uint32_t)((2 * s + b_kh) ^ b_swz)) << 4;
            uint32_t A1[4], blo[8];
            LDSM4(A1[0], A1[1], A1[2], A1[3], aH + 4096 + aoff);
            LDSM4(blo[0], blo[1], blo[2], blo[3], bLo + boff);
            LDSM4(blo[4], blo[5], blo[6], blo[7], bLo + 16 * 256 + boff);
            #pragma unroll
            for (int ni = 0; ni < 4; ++ni) {
                MMAF16(acc + 16 + ni * 4, A1[0], A1[1], A1[2], A1[3],
                       bhi[s][ni * 2], bhi[s][ni * 2 + 1]);
                MMAF16(acc + 16 + ni * 4, A1[0], A1[1], A1[2], A1[3],
                       blo[ni * 2], blo[ni * 2 + 1]);
            }
        }

        // ---- write partials to warp-private slot (no barrier needed first) ----
        {
            char* pb = smem + SCAN_P + wid * 4608;
            #pragma unroll
            for (int mi = 0; mi < 2; ++mi)
                #pragma unroll
                for (int ni = 0; ni < 4; ++ni)
                    #pragma unroll
                    for (int rh = 0; rh < 2; ++rh) {
                        const int r_l = mi * 16 + (lid >> 2) + rh * 8;
                        const int c_l = ni * 8 + (lid & 3) * 2;
                        float2 pv;
                        pv.x = acc[mi * 16 + ni * 4 + rh * 2 + 0];
                        pv.y = acc[mi * 16 + ni * 4 + rh * 2 + 1];
                        *reinterpret_cast<float2*>(pb + (r_l * 36 + c_l) * 4) = pv;
                    }
        }
        __syncthreads();                      // all partials visible

        // ---- reduce 8 partials + tanh; store A' (fp16, cross-CTA payload) ----
        float4 r;
        {
            float4 s4 = xv;
            #pragma unroll
            for (int w = 0; w < 8; ++w) {
                const float4 pv = *reinterpret_cast<const float4*>(
                    smem + SCAN_P + w * 4608 + (e_row * 36 + e_cg) * 4);
                s4.x += pv.x; s4.y += pv.y; s4.z += pv.z; s4.w += pv.w;
            }
            r.x = tanhf(s4.x);
            r.y = tanhf(s4.y);
            r.z = tanhf(s4.z);
            r.w = tanhf(s4.w);

            const size_t ao = (size_t)gm * LATENT + e0;
            *reinterpret_cast<uint32_t*>(Aw + ao + 0) = pack_h2(r.x, r.y);
            *reinterpret_cast<uint32_t*>(Aw + ao + 2) = pack_h2(r.z, r.w);
        }

        // ---- barrier: fence A' -> arrive; out_t streams during poll;
        //      warp-level release (each warp polls, then stages immediately) ----
        if (t + 1 < TT) {
            __threadfence();
            __syncthreads();                   // all A' stores fenced before arrive
            if (tid == 0) atomicAdd((unsigned*)barp, 1u);
            __stcs(reinterpret_cast<float4*>(out_t + (size_t)gm * LATENT + e0), r);
            if (lid == 0) {
                const unsigned target = (unsigned)t * 32;
                while (*barp < target) { }
            }
            __syncwarp();
        } else {
            *reinterpret_cast<float4*>(out_t + (size_t)gm * LATENT + e0) = r;
        }
    }
}

// ---------------------------------------------------------------------------
extern "C" void kernel_launch(void* const* d_in, const int* in_sizes, int n_in,
                              void* d_out, int out_size) {
    const float* x    = (const float*)d_in[0];   // [B, T, DIM]
    const float* W    = (const float*)d_in[1];   // [DIM+LATENT, LATENT]
    const float* bias = (const float*)d_in[2];   // [LATENT]
    float* out = (float*)d_out;                  // [T, B, LATENT]

    static int configured = 0;
    if (!configured) {
        cudaFuncSetAttribute(scan_kernel,
                             cudaFuncAttributeMaxDynamicSharedMemorySize, SMEM_SCAN);
        cudaFuncSetAttribute(gemm1_mma_kernel,
                             cudaFuncAttributeMaxDynamicSharedMemorySize, G1_SMEM);
        configured = 1;
    }

    // 0) weight + input fp16 splits
    prep_wh_kernel<<<dim3(32, 32), dim3(32, 8)>>>(W);
    prep_bx_kernel<<<dim3(32, 8),  dim3(32, 8)>>>(W);
    prep_x_kernel<<<(BB * TT * DIMK / 4) / 256, 256>>>(x);

    // 1) xw + bias staged into out[t, b, :] (fp16 tensor cores)
    gemm1_mma_kernel<<<BB * TT / 64, 256, G1_SMEM>>>(bias, out);

    // 2) t = 0 (+ barrier counter reset)
    tanh0_kernel<<<(BB * LATENT) / 256, 256>>>(out);

    // 3) persistent fp16 tensor-core scan for t = 1..511
    scan_kernel<<<NCTA, 256, SMEM_SCAN>>>(out);
}

// round 16
// speedup vs baseline: 1.2671x; 1.2671x over previous
#include <cuda_runtime.h>
#include <cuda_fp16.h>
#include <math.h>
#include <stdint.h>

#define DIMK   256
#define LATENT 1024
#define BB     128
#define TT     512
#define KB     2048          // B' (scan) columns: [hi | lo] fp16
#define NCTA   128

// ---------------------------------------------------------------------------
// Scratch (__device__ globals — no allocations allowed)
// ---------------------------------------------------------------------------
__device__ __half g_B[LATENT * KB];                 // scan B' = WhT split [n][hi1024|lo1024]
__device__ __half g_Ah[2][BB * LATENT];             // scan A = fp16(h), ping-pong [m][1024]
__device__ __half g_X[(size_t)BB * TT * DIMK];      // gemm1 A = fp16(x) [r][256]
__device__ __half g_BX[LATENT * 512];               // gemm1 B' = WxT split [n][hi256|lo256]
__device__ unsigned g_bar_m[128];                   // 4 m-group counters, 128B apart

__device__ __forceinline__ uint32_t smem_u32(const void* p) {
    uint32_t a;
    asm("{ .reg .u64 t; cvta.to.shared.u64 t, %1; cvt.u32.u64 %0, t; }" : "=r"(a) : "l"(p));
    return a;
}
__device__ __forceinline__ void cp16(uint32_t dst, const void* src) {
    asm volatile("cp.async.cg.shared.global [%0], [%1], 16;" :: "r"(dst), "l"(src));
}
__device__ __forceinline__ uint32_t pack_h2(float a, float b) {
    __half2 h = __floats2half2_rn(a, b);
    return *reinterpret_cast<uint32_t*>(&h);
}
#define CP_COMMIT() asm volatile("cp.async.commit_group;")
#define CP_WAIT(n)  asm volatile("cp.async.wait_group %0;" :: "n"(n))

#define LDSM4(r0, r1, r2, r3, addr) \
    asm volatile("ldmatrix.sync.aligned.m8n8.x4.shared.b16 {%0,%1,%2,%3}, [%4];" \
                 : "=r"(r0), "=r"(r1), "=r"(r2), "=r"(r3) : "r"(addr))
#define MMAF16(d, a0, a1, a2, a3, b0, b1) \
    asm volatile("mma.sync.aligned.m16n8k16.row.col.f32.f16.f16.f32 " \
                 "{%0,%1,%2,%3}, {%4,%5,%6,%7}, {%8,%9}, {%0,%1,%2,%3};" \
                 : "+f"((d)[0]), "+f"((d)[1]), "+f"((d)[2]), "+f"((d)[3]) \
                 : "r"(a0), "r"(a1), "r"(a2), "r"(a3), "r"(b0), "r"(b1))

// ---------------------------------------------------------------------------
// prep: Wh[k][n] -> g_B[n][k]=fp16 hi, g_B[n][1024+k]=fp16 lo
// ---------------------------------------------------------------------------
__global__ void prep_wh_kernel(const float* __restrict__ W) {
    const float* Wh = W + (size_t)DIMK * LATENT;
    __shared__ float tile[32][33];
    int bx = blockIdx.x * 32;
    int by = blockIdx.y * 32;
    int tx = threadIdx.x, ty = threadIdx.y;
    #pragma unroll
    for (int i = ty; i < 32; i += 8)
        tile[i][tx] = Wh[(size_t)(by + i) * LATENT + bx + tx];
    __syncthreads();
    #pragma unroll
    for (int i = ty; i < 32; i += 8) {
        float v = tile[tx][i];
        size_t o = (size_t)(bx + i) * KB + by + tx;
        __half h = __float2half_rn(v);
        g_B[o]        = h;
        g_B[o + 1024] = __float2half_rn(v - __half2float(h));
    }
}

// ---------------------------------------------------------------------------
// prep: Wx[k][n] (k<256) -> g_BX[n][k]=fp16 hi, [n][256+k]=fp16 lo
// ---------------------------------------------------------------------------
__global__ void prep_bx_kernel(const float* __restrict__ W) {
    __shared__ float tile[32][33];
    int bx = blockIdx.x * 32;
    int by = blockIdx.y * 32;
    int tx = threadIdx.x, ty = threadIdx.y;
    #pragma unroll
    for (int i = ty; i < 32; i += 8)
        tile[i][tx] = W[(size_t)(by + i) * LATENT + bx + tx];
    __syncthreads();
    #pragma unroll
    for (int i = ty; i < 32; i += 8) {
        float v = tile[tx][i];
        size_t o = (size_t)(bx + i) * 512 + by + tx;
        __half h = __float2half_rn(v);
        g_BX[o]       = h;
        g_BX[o + 256] = __float2half_rn(v - __half2float(h));
    }
}

// ---------------------------------------------------------------------------
// prep: x[r][d] fp32 -> g_X[r][d] = fp16(x) (unsplit; error carried by W split)
// ---------------------------------------------------------------------------
__global__ void prep_x_kernel(const float* __restrict__ x) {
    size_t idx = (size_t)blockIdx.x * 256 + threadIdx.x;
    size_t e = idx * 4;
    float4 v = *reinterpret_cast<const float4*>(x + e);
    *reinterpret_cast<uint32_t*>(&g_X[e + 0]) = pack_h2(v.x, v.y);
    *reinterpret_cast<uint32_t*>(&g_X[e + 2]) = pack_h2(v.z, v.w);
}

// ---------------------------------------------------------------------------
// GEMM1 (tensor, fp16; round-12 config — 258us): out[t,b,:] = x @ Wx + b.
// K'=512 ([Whi256|Wlo256], A=fp16 x unsplit). CTA 64 rows, warp 32x16,
// A resident 32KB, B double-buffered 2x16KB, 2 CTAs/SM.
// ---------------------------------------------------------------------------
#define G1_SMB   32768
#define G1_SMEM  (32768 + 2 * 16384)

__global__ void __launch_bounds__(256, 2)
gemm1_mma_kernel(const float* __restrict__ bias, float* __restrict__ out) {
    extern __shared__ char smem[];
    const uint32_t smA = smem_u32(smem);
    const uint32_t smB = smA + G1_SMB;
    const int tid = threadIdx.x;
    const int lid = tid & 31;
    const int wid = tid >> 5;
    const int r0 = blockIdx.x * 64;

    {
        const __half* gA = g_X + (size_t)r0 * DIMK;
        #pragma unroll
        for (int j = 0; j < 8; ++j) {
            int ci = tid + j * 256;
            int ch = ci >> 10;
            int rem = ci & 1023;
            int rw = rem >> 4;
            int cc = rem & 15;
            cp16(smA + ch * 16384 + rw * 256 + (((cc ^ (rw & 15))) << 4),
                 gA + (size_t)rw * DIMK + ch * 128 + cc * 8);
        }
        CP_COMMIT();
    }
    {
        #pragma unroll
        for (int j = 0; j < 4; ++j) {
            int ci = tid + j * 256;
            int rw = ci >> 4;
            int cc = ci & 15;
            cp16(smB + rw * 256 + (((cc ^ (rw & 15))) << 4),
                 g_BX + (size_t)rw * 512 + cc * 8);
        }
        CP_COMMIT();
    }

    const int wm = wid & 1;
    const int wn = wid >> 1;
    const int a_row0 = wm * 32 + (lid & 15);
    const int a_row1 = a_row0 + 16;
    const int a_kh   = (lid >> 4) & 1;
    const int b_row  = wn * 16 + (((lid >> 4) & 1) << 3) + (lid & 7);
    const int b_kh   = (lid >> 3) & 1;
    const int a_swz0 = a_row0 & 15, a_swz1 = a_row1 & 15, b_swz = b_row & 15;
    const int g8 = lid >> 2;
    const int q  = lid & 3;

    float acc[4][4];

    #pragma unroll 1
    for (int gg = 0; gg < 64; ++gg) {
        const int nt = gg >> 2;
        const int c  = gg & 3;

        if (gg + 1 < 64) {
            const int nt2 = (gg + 1) >> 2;
            const int c2  = (gg + 1) & 3;
            const int cb  = c2 * 128;
            uint32_t dst = smB + ((gg + 1) & 1) * 16384;
            const __half* gBn = g_BX + (size_t)(nt2 * 64) * 512;
            #pragma unroll
            for (int j = 0; j < 4; ++j) {
                int ci = tid + j * 256;
                int rw = ci >> 4;
                int cc = ci & 15;
                cp16(dst + rw * 256 + (((cc ^ (rw & 15))) << 4),
                     gBn + (size_t)rw * 512 + cb + cc * 8);
            }
            CP_COMMIT();
            CP_WAIT(1);
        } else {
            CP_WAIT(0);
        }
        __syncthreads();

        if (c == 0) {
            #pragma unroll
            for (int i = 0; i < 4; ++i)
                #pragma unroll
                for (int j = 0; j < 4; ++j) acc[i][j] = 0.f;
        }

        const int ach = c & 1;
        const uint32_t aR0 = smA + ach * 16384 + a_row0 * 256;
        const uint32_t aR1 = smA + ach * 16384 + a_row1 * 256;
        const uint32_t bR  = smB + (gg & 1) * 16384 + b_row * 256;

        #pragma unroll
        for (int s = 0; s < 8; ++s) {
            uint32_t A0, A1, A2, A3, C0, C1, C2, C3, B0, B1, B2, B3;
            LDSM4(A0, A1, A2, A3, aR0 + (((2 * s + a_kh) ^ a_swz0) << 4));
            LDSM4(C0, C1, C2, C3, aR1 + (((2 * s + a_kh) ^ a_swz1) << 4));
            LDSM4(B0, B1, B2, B3, bR  + (((2 * s + b_kh) ^ b_swz) << 4));
            MMAF16(acc[0], A0, A1, A2, A3, B0, B1);
            MMAF16(acc[1], A0, A1, A2, A3, B2, B3);
            MMAF16(acc[2], C0, C1, C2, C3, B0, B1);
            MMAF16(acc[3], C0, C1, C2, C3, B2, B3);
        }

        if (c == 3) {
            const int n0 = nt * 64;
            #pragma unroll
            for (int f = 0; f < 2; ++f) {
                #pragma unroll
                for (int ntf = 0; ntf < 2; ++ntf) {
                    const int col = n0 + wn * 16 + ntf * 8 + q * 2;
                    float2 bv = *reinterpret_cast<const float2*>(bias + col);
                    #pragma unroll
                    for (int rh = 0; rh < 2; ++rh) {
                        const int r = r0 + wm * 32 + f * 16 + g8 + rh * 8;
                        const int bi = r >> 9;
                        const int ti = r & (TT - 1);
                        float2 o;
                        o.x = acc[f * 2 + ntf][rh * 2 + 0] + bv.x;
                        o.y = acc[f * 2 + ntf][rh * 2 + 1] + bv.y;
                        *reinterpret_cast<float2*>(
                            &out[((size_t)ti * BB + bi) * LATENT + col]) = o;
                    }
                }
            }
        }
        __syncthreads();
    }
}

// ---------------------------------------------------------------------------
// t = 0: out[0] = tanh(out[0]); h0 -> g_Ah[0] fp16; reset m-group barriers
// ---------------------------------------------------------------------------
__global__ void tanh0_kernel(float* __restrict__ out0) {
    int i = blockIdx.x * blockDim.x + threadIdx.x;
    if (i < 4) g_bar_m[i * 32] = 0;
    float v = tanhf(out0[i]);
    out0[i] = v;
    g_Ah[0][i] = __float2half_rn(v);
}

// ---------------------------------------------------------------------------
// Persistent scan: 128 CTAs (4m x 32n tiles of 32x32), 256 threads = 8 warps.
// 8-way split-K, 2 fp16 terms: A*Bhi(reg) + A*Blo(smem), A = fp16(h) unsplit.
// Round-14 sync scheme (tid0 poll + block-sync release, deferred __stcs out),
// plus DEDICATED partials buffer: warps dump partials right after their MMAs
// (no pre-exchange barrier) -> 3 block syncs per step instead of 4.
// ---------------------------------------------------------------------------
#define SCAN_A    65536                       // A region: 8 x 8KB (after Blo 8 x 8KB)
#define SCAN_P    131072                      // partials: 8 warps x 4608B
#define SMEM_SCAN (131072 + 8 * 4608)         // 167936

__global__ void __launch_bounds__(256, 1)
scan_kernel(float* __restrict__ out) {
    extern __shared__ char smem[];
    const int tid = threadIdx.x;
    const int lid = tid & 31;
    const int wid = tid >> 5;
    const int bid = blockIdx.x;
    const int mg = bid & 3;
    const int m0 = mg * 32;
    const int n0 = (bid >> 2) * 32;
    const uint32_t smB = smem_u32(smem);
    const uint32_t smA = smB + SCAN_A;
    const uint32_t abase = smA + wid * 8192;      // this warp's A slot (32 rows x 256B)

    // ---- B geometry ----
    const int b_r  = (((lid >> 4) & 1) << 3) + (lid & 7);
    const int b_kh = (lid >> 3) & 1;
    const int b_swz = b_r & 15;
    // ---- A geometry ----
    const int a_r  = lid & 15;
    const int a_kh = (lid >> 4) & 1;
    const int a_swz = a_r & 15;

    // ---- init: warp w stages B-lo chunk w (resident) + B-hi chunk w (temp) ----
    {
        const __half* gB = g_B + (size_t)n0 * KB;
        #pragma unroll
        for (int j = 0; j < 16; ++j) {
            int ci = lid + j * 32;        // 0..511
            int rw = ci >> 4;
            int cc = ci & 15;
            uint32_t sw = ((cc ^ (rw & 15)) << 4);
            cp16(smB + wid * 8192 + rw * 256 + sw,
                 gB + (size_t)rw * KB + 1024 + wid * 128 + cc * 8);   // lo
            cp16(abase + rw * 256 + sw,
                 gB + (size_t)rw * KB + wid * 128 + cc * 8);          // hi (temp)
        }
        CP_COMMIT();
        CP_WAIT(0);
        __syncwarp();
    }

    // ---- B-hi fragments into registers (constant for all 511 steps) ----
    uint32_t bhi[8][8];
    #pragma unroll
    for (int s = 0; s < 8; ++s) {
        const uint32_t off = ((uint32_t)((2 * s + b_kh) ^ b_swz)) << 4;
        LDSM4(bhi[s][0], bhi[s][1], bhi[s][2], bhi[s][3], abase + b_r * 256 + off);
        LDSM4(bhi[s][4], bhi[s][5], bhi[s][6], bhi[s][7], abase + (b_r + 16) * 256 + off);
    }
    __syncwarp();

    // ---- epilogue geometry ----
    const int e_row = tid >> 3;            // 0..31
    const int e_cg  = (tid & 7) * 4;       // 0..28
    const int gm = m0 + e_row;
    const int e0 = n0 + e_cg;
    volatile unsigned* barp = &g_bar_m[mg * 32];

    for (int t = 1; t < TT; ++t) {
        const int rp = (t - 1) & 1;
        const __half* Ar = g_Ah[rp];
        __half* Aw = g_Ah[rp ^ 1];
        float* out_t = out + (size_t)t * BB * LATENT;

        // ---- self-stage A chunk: group 0 = rows 0-15, group 1 = rows 16-31 ----
        #pragma unroll
        for (int j = 0; j < 8; ++j) {
            int ci = lid + j * 32;            // 0..255
            int rw = ci >> 4;                 // 0..15
            int cc = ci & 15;
            cp16(abase + rw * 256 + ((cc ^ (rw & 15)) << 4),
                 Ar + (size_t)(m0 + rw) * LATENT + wid * 128 + cc * 8);
        }
        CP_COMMIT();
        #pragma unroll
        for (int j = 0; j < 8; ++j) {
            int ci = lid + j * 32;
            int rw = ci >> 4;
            int cc = ci & 15;
            cp16(abase + 4096 + rw * 256 + ((cc ^ (rw & 15)) << 4),
                 Ar + (size_t)(m0 + 16 + rw) * LATENT + wid * 128 + cc * 8);
        }
        CP_COMMIT();

        // ---- xw prefetch (hidden under staging + MMA) ----
        const float4 xv = *reinterpret_cast<const float4*>(
            out_t + (size_t)gm * LATENT + e0);

        float acc[32];
        #pragma unroll
        for (int i = 0; i < 32; ++i) acc[i] = 0.f;

        const uint32_t aH = abase + a_r * 256;
        const uint32_t bLo = smB + wid * 8192 + b_r * 256;

        // ---- phase 1: m-frag0 (rows 0-15) while group 1 streams in ----
        CP_WAIT(1);
        __syncwarp();
        #pragma unroll
        for (int s = 0; s < 8; ++s) {
            const uint32_t aoff = ((uint32_t)((2 * s + a_kh) ^ a_swz)) << 4;
            const uint32_t boff = ((uint32_t)((2 * s + b_kh) ^ b_swz)) << 4;
            uint32_t A0[4], blo[8];
            LDSM4(A0[0], A0[1], A0[2], A0[3], aH + aoff);
            LDSM4(blo[0], blo[1], blo[2], blo[3], bLo + boff);
            LDSM4(blo[4], blo[5], blo[6], blo[7], bLo + 16 * 256 + boff);
            #pragma unroll
            for (int ni = 0; ni < 4; ++ni) {
                MMAF16(acc + ni * 4, A0[0], A0[1], A0[2], A0[3],
                       bhi[s][ni * 2], bhi[s][ni * 2 + 1]);
                MMAF16(acc + ni * 4, A0[0], A0[1], A0[2], A0[3],
                       blo[ni * 2], blo[ni * 2 + 1]);
            }
        }

        // ---- phase 2: m-frag1 (rows 16-31) ----
        CP_WAIT(0);
        __syncwarp();
        #pragma unroll
        for (int s = 0; s < 8; ++s) {
            const uint32_t aoff = ((uint32_t)((2 * s + a_kh) ^ a_swz)) << 4;
            const uint32_t boff = ((uint32_t)((2 * s + b_kh) ^ b_swz)) << 4;
            uint32_t A1[4], blo[8];
            LDSM4(A1[0], A1[1], A1[2], A1[3], aH + 4096 + aoff);
            LDSM4(blo[0], blo[1], blo[2], blo[3], bLo + boff);
            LDSM4(blo[4], blo[5], blo[6], blo[7], bLo + 16 * 256 + boff);
            #pragma unroll
            for (int ni = 0; ni < 4; ++ni) {
                MMAF16(acc + 16 + ni * 4, A1[0], A1[1], A1[2], A1[3],
                       bhi[s][ni * 2], bhi[s][ni * 2 + 1]);
                MMAF16(acc + 16 + ni * 4, A1[0], A1[1], A1[2], A1[3],
                       blo[ni * 2], blo[ni * 2 + 1]);
            }
        }

        // ---- dump partials to warp-private dedicated slot (no pre-barrier) ----
        {
            char* pb = smem + SCAN_P + wid * 4608;
            #pragma unroll
            for (int mi = 0; mi < 2; ++mi)
                #pragma unroll
                for (int ni = 0; ni < 4; ++ni)
                    #pragma unroll
                    for (int rh = 0; rh < 2; ++rh) {
                        const int r_l = mi * 16 + (lid >> 2) + rh * 8;
                        const int c_l = ni * 8 + (lid & 3) * 2;
                        float2 pv;
                        pv.x = acc[mi * 16 + ni * 4 + rh * 2 + 0];
                        pv.y = acc[mi * 16 + ni * 4 + rh * 2 + 1];
                        *reinterpret_cast<float2*>(pb + (r_l * 36 + c_l) * 4) = pv;
                    }
        }
        __syncthreads();                      // all partials visible

        // ---- reduce 8 partials + tanh; store A' (fp16, cross-CTA payload) ----
        float4 r;
        {
            float4 s4 = xv;
            #pragma unroll
            for (int w = 0; w < 8; ++w) {
                const float4 pv = *reinterpret_cast<const float4*>(
                    smem + SCAN_P + w * 4608 + (e_row * 36 + e_cg) * 4);
                s4.x += pv.x; s4.y += pv.y; s4.z += pv.z; s4.w += pv.w;
            }
            r.x = tanhf(s4.x);
            r.y = tanhf(s4.y);
            r.z = tanhf(s4.z);
            r.w = tanhf(s4.w);

            const size_t ao = (size_t)gm * LATENT + e0;
            *reinterpret_cast<uint32_t*>(Aw + ao + 0) = pack_h2(r.x, r.y);
            *reinterpret_cast<uint32_t*>(Aw + ao + 2) = pack_h2(r.z, r.w);
        }

        // ---- barrier (round-14 proven): fence A' -> arrive; out_t streams
        //      during tid0 poll; block-sync release ----
        if (t + 1 < TT) {
            __threadfence();
            __syncthreads();
            if (tid == 0) atomicAdd((unsigned*)barp, 1u);
            __stcs(reinterpret_cast<float4*>(out_t + (size_t)gm * LATENT + e0), r);
            if (tid == 0) {
                const unsigned target = (unsigned)t * 32;
                while (*barp < target) { }
            }
            __syncthreads();
        } else {
            *reinterpret_cast<float4*>(out_t + (size_t)gm * LATENT + e0) = r;
        }
    }
}

// ---------------------------------------------------------------------------
extern "C" void kernel_launch(void* const* d_in, const int* in_sizes, int n_in,
                              void* d_out, int out_size) {
    const float* x    = (const float*)d_in[0];   // [B, T, DIM]
    const float* W    = (const float*)d_in[1];   // [DIM+LATENT, LATENT]
    const float* bias = (const float*)d_in[2];   // [LATENT]
    float* out = (float*)d_out;                  // [T, B, LATENT]

    static int configured = 0;
    if (!configured) {
        cudaFuncSetAttribute(scan_kernel,
                             cudaFuncAttributeMaxDynamicSharedMemorySize, SMEM_SCAN);
        cudaFuncSetAttribute(gemm1_mma_kernel,
                             cudaFuncAttributeMaxDynamicSharedMemorySize, G1_SMEM);
        configured = 1;
    }

    // 0) weight + input fp16 splits
    prep_wh_kernel<<<dim3(32, 32), dim3(32, 8)>>>(W);
    prep_bx_kernel<<<dim3(32, 8),  dim3(32, 8)>>>(W);
    prep_x_kernel<<<(BB * TT * DIMK / 4) / 256, 256>>>(x);

    // 1) xw + bias staged into out[t, b, :] (fp16 tensor cores)
    gemm1_mma_kernel<<<BB * TT / 64, 256, G1_SMEM>>>(bias, out);

    // 2) t = 0 (+ barrier counter reset)
    tanh0_kernel<<<(BB * LATENT) / 256, 256>>>(out);

    // 3) persistent fp16 tensor-core scan for t = 1..511
    scan_kernel<<<NCTA, 256, SMEM_SCAN>>>(out);
}